// round 17
// baseline (speedup 1.0000x reference)
#include <cuda_runtime.h>
#include <cuda_bf16.h>
#include <math.h>
#include <stdint.h>

#define NB 16
#define HB 200
#define EMBD 64
#define H1D 128
#define H1P 129                  // padded row stride for W1 tiles (bank-conflict fix)
#define H2D 64
#define PP 19900                 // H*(H-1)/2
#define ROWS (NB*HB)             // 3200
#define TOTPAIRS (NB*PP)         // 318400
#define W1COLS 134               // 2*EMB + 6

#define RPB 10                   // rows per prep block
#define PREPBLK 320
#define PTHREADS 256             // 8 warps; 2 blocks/SM; 128 regs/thread

#define NTILES ((TOTPAIRS + 127) / 128)   // 2488
#define TCGRID 304

#define HSTRIDE_B 272            // h row stride in bytes (128 bf16 + 8 pad)
#define A_HI_OFF 0
#define A_LO_OFF 34816           // 128*272
#define RED_OFF  69632           // + 128*272
#define SMEM_DYN (RED_OFF + 4*128*4)   // 71680

// scratch (device globals; no allocation allowed)
__device__ float g_A[ROWS*H1D];      // e_i @ W1a^T
__device__ float g_B[ROWS*H1D];      // e_j @ W1b^T
__device__ float g_catb[6*H1D];      // W1c[:,cat] + b1
__device__ float g_sim[TOTPAIRS];

__device__ __forceinline__ uint32_t smem_to_u32(const void* p) {
    uint32_t a;
    asm("{ .reg .u64 t; cvta.to.shared.u64 t, %1; cvt.u32.u64 %0, t; }"
        : "=r"(a) : "l"(p));
    return a;
}

__device__ __forceinline__ void ldmatrix_x4(uint32_t& r0, uint32_t& r1,
                                            uint32_t& r2, uint32_t& r3,
                                            uint32_t addr) {
    asm volatile("ldmatrix.sync.aligned.m8n8.x4.shared.b16 {%0,%1,%2,%3}, [%4];"
                 : "=r"(r0), "=r"(r1), "=r"(r2), "=r"(r3) : "r"(addr));
}

__device__ __forceinline__ void mma_bf16(float& d0, float& d1, float& d2, float& d3,
                                         uint32_t a0, uint32_t a1, uint32_t a2, uint32_t a3,
                                         uint32_t b0, uint32_t b1) {
    asm volatile("mma.sync.aligned.m16n8k16.row.col.f32.bf16.bf16.f32 "
                 "{%0,%1,%2,%3}, {%4,%5,%6,%7}, {%8,%9}, {%0,%1,%2,%3};"
                 : "+f"(d0), "+f"(d1), "+f"(d2), "+f"(d3)
                 : "r"(a0), "r"(a1), "r"(a2), "r"(a3), "r"(b0), "r"(b1));
}

// ---------------------------------------------------------------------------
// Kernel A (ILP v3): 320 blocks x 256 threads, 2 blocks/SM, <=128 regs.
// Each thread computes 5 rows (10 indep FMA chains); W-loads amortized 5x.
// Staging: warp-per-row (no integer div), coalesced LDG, conflict-free STS.
// ---------------------------------------------------------------------------
__global__ void __launch_bounds__(PTHREADS, 2)
prep_kernel(const int* __restrict__ skills,
            const float* __restrict__ emb,
            const float* __restrict__ W1,
            const float* __restrict__ b1) {
    extern __shared__ float psm[];
    float* W1aT = psm;                 // [k][c] 64x129 (padded)
    float* W1bT = W1aT + EMBD*H1P;     // [k][c] 64x129 (padded)
    float* es   = W1bT + EMBD*H1P;     // [row][k] RPB x 64
    __shared__ int sk[RPB];

    int tid = threadIdx.x, wid = tid >> 5, lane = tid & 31;
    int r0  = blockIdx.x * RPB;

    // stage W1: warp per matrix-row c; lanes span j (coalesced LDG,
    // STS banks (j + c) % 32 -> conflict-free)
    for (int c = wid; c < H1D; c += 8) {
        const float* src = W1 + c*W1COLS;
        for (int j = lane; j < W1COLS; j += 32) {
            float v = src[j];
            if (j < EMBD)            W1aT[j*H1P + c] = v;
            else if (j < 2*EMBD)     W1bT[(j-EMBD)*H1P + c] = v;
            else if (blockIdx.x == 0) g_catb[(j-2*EMBD)*H1D + c] = v + b1[c];
        }
    }
    if (tid < RPB) sk[tid] = skills[r0 + tid];
    __syncthreads();
    for (int idx = tid; idx < RPB*EMBD; idx += PTHREADS) {
        int row = idx >> 6, k = idx & 63;
        es[row*EMBD + k] = emb[sk[row]*EMBD + k];
    }
    __syncthreads();

    int c  = tid & 127;
    int rg = tid >> 7;                 // 0,1 -> rows rg*5 .. rg*5+4
    const float* eb = es + rg*5*EMBD;
    float aa[5], bb[5];
#pragma unroll
    for (int r = 0; r < 5; r++) { aa[r] = 0.f; bb[r] = 0.f; }
#pragma unroll 8
    for (int k = 0; k < EMBD; k++) {
        float wa = W1aT[k*H1P + c];
        float wb = W1bT[k*H1P + c];
#pragma unroll
        for (int r = 0; r < 5; r++) {
            float ev = eb[r*EMBD + k];
            aa[r] = fmaf(ev, wa, aa[r]);
            bb[r] = fmaf(ev, wb, bb[r]);
        }
    }
#pragma unroll
    for (int r = 0; r < 5; r++) {
        int row = r0 + rg*5 + r;
        g_A[row*H1D + c] = aa[r];
        g_B[row*H1D + c] = bb[r];
    }
}

// ---------------------------------------------------------------------------
// Kernel B: tile = 128 pairs x 64 outputs. 2 syncthreads per tile (3rd
// barrier removed: reduce & next phase-1 touch disjoint smem; S1 orders
// reduce vs next MMA's red writes).
// ---------------------------------------------------------------------------
__global__ void __launch_bounds__(256, 2)
pair_tc_kernel(const int* __restrict__ skills,
               const float* __restrict__ ts,
               const float* __restrict__ W2,
               const float* __restrict__ b2,
               const float* __restrict__ W3,
               const float* __restrict__ b3) {
    extern __shared__ __align__(16) char smem[];
    float* red = (float*)(smem + RED_OFF);     // [4][128]

    __shared__ float catbs[6*H1D];
    __shared__ float b2s[H2D], W3s[H2D];
    __shared__ float b3s_sh;

    int tid = threadIdx.x, wid = tid >> 5, lane = tid & 31;
    int g = lane >> 2, t = lane & 3;
    int mhalf = wid >> 2;          // 0,1 : rows [64*mhalf, 64*mhalf+64)
    int nq    = wid & 3;           // 0..3: cols [16*nq, 16*nq+16)
    int n0    = nq * 16;

    for (int idx = tid; idx < 6*H1D; idx += 256) catbs[idx] = g_catb[idx];
    if (tid < H2D) { b2s[tid] = b2[tid]; W3s[tid] = W3[tid]; }
    if (tid == 0) b3s_sh = b3[0];

    // ---- W2 hi/lo B-fragments: ng=0 -> col n0+g, ng=1 -> col n0+8+g ----
    uint32_t bH[8][4], bL[8][4];
#pragma unroll
    for (int ng = 0; ng < 2; ng++) {
        const float* wrow = W2 + (n0 + ng*8 + g) * H1D;
#pragma unroll
        for (int kt = 0; kt < 8; kt++) {
#pragma unroll
            for (int hb = 0; hb < 2; hb++) {
                int k0 = kt*16 + t*2 + hb*8;
                float w0 = wrow[k0], w1 = wrow[k0+1];
                __nv_bfloat16 h0 = __float2bfloat16(w0);
                __nv_bfloat16 h1 = __float2bfloat16(w1);
                __nv_bfloat162 hp; hp.x = h0; hp.y = h1;
                __nv_bfloat162 lp = __floats2bfloat162_rn(w0 - __bfloat162float(h0),
                                                          w1 - __bfloat162float(h1));
                bH[kt][ng*2+hb] = *reinterpret_cast<uint32_t*>(&hp);
                bL[kt][ng*2+hb] = *reinterpret_cast<uint32_t*>(&lp);
            }
        }
    }
    __syncthreads();

    uint32_t smem_base = smem_to_u32(smem);
    float b2c[2][2], w3c[2][2];
#pragma unroll
    for (int ng = 0; ng < 2; ng++) {
        b2c[ng][0] = b2s[n0 + ng*8 + t*2];
        b2c[ng][1] = b2s[n0 + ng*8 + t*2 + 1];
        w3c[ng][0] = W3s[n0 + ng*8 + t*2];
        w3c[ng][1] = W3s[n0 + ng*8 + t*2 + 1];
    }

    for (int tile = blockIdx.x; tile < NTILES; tile += TCGRID) {
        // ---- phase 1: per-lane pair indices for u = lane&15, then broadcast ----
        int ri_l, rj_l, cat_l;
        {
            int u_l = lane & 15;
            int pq = tile*128 + wid*16 + u_l;
            int q  = (pq < TOTPAIRS) ? pq : (TOTPAIRS - 1);
            int n  = q / PP, p = q - n*PP;
            int i = (int)((1.0f + sqrtf(1.0f + 8.0f*(float)p)) * 0.5f);
            while (i*(i-1)/2 > p)  --i;
            while ((i+1)*i/2 <= p) ++i;
            int j = p - i*(i-1)/2;
            ri_l = n*HB + i;
            rj_l = n*HB + j;
            float dt = ts[ri_l] - ts[rj_l];
            cat_l = 1 + (dt > 1.f) + (dt > 3600.f) + (dt > 86400.f) + (dt > 604800.f);
            if (skills[ri_l] == 0 || skills[rj_l] == 0) cat_l = 0;
        }
        {
            int c0 = lane * 4;
            char* baseHi = smem + A_HI_OFF + (wid*16)*HSTRIDE_B + c0*2;
            char* baseLo = smem + A_LO_OFF + (wid*16)*HSTRIDE_B + c0*2;
#pragma unroll 4
            for (int u = 0; u < 16; u++) {
                int ri  = __shfl_sync(0xffffffffu, ri_l, u);
                int rj  = __shfl_sync(0xffffffffu, rj_l, u);
                int cat = __shfl_sync(0xffffffffu, cat_l, u);
                float4 av = *(const float4*)(g_A + ri*H1D + c0);
                float4 bv = *(const float4*)(g_B + rj*H1D + c0);
                float4 cv = *(const float4*)(catbs + cat*H1D + c0);
                float h0 = fmaxf(av.x + bv.x + cv.x, 0.f);
                float h1 = fmaxf(av.y + bv.y + cv.y, 0.f);
                float h2 = fmaxf(av.z + bv.z + cv.z, 0.f);
                float h3 = fmaxf(av.w + bv.w + cv.w, 0.f);
                __nv_bfloat162 hp0; hp0.x = __float2bfloat16(h0); hp0.y = __float2bfloat16(h1);
                __nv_bfloat162 hp1; hp1.x = __float2bfloat16(h2); hp1.y = __float2bfloat16(h3);
                float2 f0 = __bfloat1622float2(hp0);
                float2 f1 = __bfloat1622float2(hp1);
                __nv_bfloat162 lp0 = __floats2bfloat162_rn(h0 - f0.x, h1 - f0.y);
                __nv_bfloat162 lp1 = __floats2bfloat162_rn(h2 - f1.x, h3 - f1.y);
                uint2 hv, lv;
                hv.x = *reinterpret_cast<uint32_t*>(&hp0);
                hv.y = *reinterpret_cast<uint32_t*>(&hp1);
                lv.x = *reinterpret_cast<uint32_t*>(&lp0);
                lv.y = *reinterpret_cast<uint32_t*>(&lp1);
                *(uint2*)(baseHi + u*HSTRIDE_B) = hv;
                *(uint2*)(baseLo + u*HSTRIDE_B) = lv;
            }
        }
        __syncthreads();   // S1: h tile complete (also orders prev reduce vs red rewrite)

        // ---- MMA: warp covers rows [64*mhalf, +64), cols [16*nq, +16) ----
        {
            uint32_t laddrHi = smem_base + A_HI_OFF
                             + (uint32_t)(mhalf*64 + (lane & 15)) * HSTRIDE_B
                             + (uint32_t)(lane >> 4) * 16;
            uint32_t laddrLo = laddrHi + (A_LO_OFF - A_HI_OFF);
#pragma unroll
            for (int mt = 0; mt < 4; mt++) {
                float d[2][4];
#pragma unroll
                for (int ng = 0; ng < 2; ng++)
#pragma unroll
                    for (int x = 0; x < 4; x++) d[ng][x] = 0.f;
                uint32_t mOff = (uint32_t)(mt*16) * HSTRIDE_B;
#pragma unroll
                for (int kt = 0; kt < 8; kt++) {
                    uint32_t aH0,aH1,aH2,aH3, aL0,aL1,aL2,aL3;
                    ldmatrix_x4(aH0,aH1,aH2,aH3, laddrHi + mOff + kt*32);
                    ldmatrix_x4(aL0,aL1,aL2,aL3, laddrLo + mOff + kt*32);
#pragma unroll
                    for (int ng = 0; ng < 2; ng++) {
                        uint32_t h0 = bH[kt][ng*2], h1 = bH[kt][ng*2+1];
                        uint32_t l0 = bL[kt][ng*2], l1 = bL[kt][ng*2+1];
                        mma_bf16(d[ng][0],d[ng][1],d[ng][2],d[ng][3],
                                 aH0,aH1,aH2,aH3, h0, h1);
                        mma_bf16(d[ng][0],d[ng][1],d[ng][2],d[ng][3],
                                 aL0,aL1,aL2,aL3, h0, h1);
                        mma_bf16(d[ng][0],d[ng][1],d[ng][2],d[ng][3],
                                 aH0,aH1,aH2,aH3, l0, l1);
                    }
                }
                float p0 = fmaf(fmaxf(d[0][0] + b2c[0][0], 0.f), w3c[0][0],
                                fmaxf(d[0][1] + b2c[0][1], 0.f) * w3c[0][1]);
                p0 = fmaf(fmaxf(d[1][0] + b2c[1][0], 0.f), w3c[1][0], p0);
                p0 = fmaf(fmaxf(d[1][1] + b2c[1][1], 0.f), w3c[1][1], p0);
                float p1 = fmaf(fmaxf(d[0][2] + b2c[0][0], 0.f), w3c[0][0],
                                fmaxf(d[0][3] + b2c[0][1], 0.f) * w3c[0][1]);
                p1 = fmaf(fmaxf(d[1][2] + b2c[1][0], 0.f), w3c[1][0], p1);
                p1 = fmaf(fmaxf(d[1][3] + b2c[1][1], 0.f), w3c[1][1], p1);
                p0 += __shfl_xor_sync(0xffffffffu, p0, 1);
                p0 += __shfl_xor_sync(0xffffffffu, p0, 2);
                p1 += __shfl_xor_sync(0xffffffffu, p1, 1);
                p1 += __shfl_xor_sync(0xffffffffu, p1, 2);
                if (t == 0) {
                    int r0 = mhalf*64 + mt*16 + g;
                    red[nq*128 + r0]     = p0;
                    red[nq*128 + r0 + 8] = p1;
                }
            }
        }
        __syncthreads();   // S2: red complete, A consumed

        if (tid < 128) {
            int pq = tile*128 + tid;
            if (pq < TOTPAIRS) {
                float s = red[tid] + red[128 + tid] + red[256 + tid] + red[384 + tid];
                g_sim[pq] = tanhf(s + b3s_sh);
            }
        }
        // no 3rd barrier: next phase-1 writes A (disjoint from red); S1 orders
        // this reduce against the next tile's red writes.
    }
}

// ---------------------------------------------------------------------------
// Kernel C (fused seg+final): warp per row r. (unchanged)
// ---------------------------------------------------------------------------
__global__ void final_kernel(const float* __restrict__ users,
                             const float* __restrict__ items,
                             const float* __restrict__ langs,
                             const int* __restrict__ skills,
                             const float* __restrict__ targets,
                             const int* __restrict__ mask,
                             const float* __restrict__ linW,
                             const float* __restrict__ linb,
                             float* __restrict__ out) {
    int r    = (blockIdx.x*blockDim.x + threadIdx.x) >> 5;
    int lane = threadIdx.x & 31;
    if (r >= ROWS) return;
    int n = r / HB, i = r % HB;

    const float* sp = g_sim + n*PP + i*(i-1)/2;
    float s = 0.f;
    for (int k = lane; k < i; k += 32) s += sp[k];

    float acc = 0.f;
    const float* u = users + n*100;
    for (int k = lane; k < 100; k += 32) acc = fmaf(u[k], linW[k], acc);
    const float* it = items + r*100;
    for (int k = lane; k < 100; k += 32) acc = fmaf(it[k], linW[100+k], acc);
    if (lane < 10) acc = fmaf(langs[r*10 + lane], linW[200 + lane], acc);

#pragma unroll
    for (int sh = 16; sh > 0; sh >>= 1) {
        s   += __shfl_xor_sync(0xffffffffu, s,   sh);
        acc += __shfl_xor_sync(0xffffffffu, acc, sh);
    }
    if (lane == 0) {
        int sidx = skills[r];
        float label = targets[r];
        float vt = (sidx != 0) ? s : 0.f;
        float vc = vt * label;
        float logit = acc + linW[210 + sidx]
                    + vt*linW[2210 + sidx]
                    + vc*linW[4210 + sidx]
                    + linb[0];
        float maskf = (mask[r] != 0) ? 1.f : 0.f;
        float bce   = fmaxf(logit, 0.f) - logit*label + log1pf(expf(-fabsf(logit)));
        out[r]          = bce * maskf;
        out[ROWS + r]   = 1.f / (1.f + expf(-logit));
        out[2*ROWS + r] = label;
    }
}

// ---------------------------------------------------------------------------
extern "C" void kernel_launch(void* const* d_in, const int* in_sizes, int n_in,
                              void* d_out, int out_size) {
    const float* users    = (const float*)d_in[0];
    const float* items    = (const float*)d_in[1];
    const float* langs    = (const float*)d_in[2];
    const int*   skills   = (const int*)  d_in[3];
    const float* ts       = (const float*)d_in[4];
    const float* targets  = (const float*)d_in[5];
    const int*   mask     = (const int*)  d_in[6];
    const float* emb      = (const float*)d_in[7];
    const float* W1       = (const float*)d_in[8];
    const float* b1       = (const float*)d_in[9];
    const float* W2       = (const float*)d_in[10];
    const float* b2       = (const float*)d_in[11];
    const float* W3       = (const float*)d_in[12];
    const float* b3       = (const float*)d_in[13];
    const float* linW     = (const float*)d_in[14];
    const float* linb     = (const float*)d_in[15];
    float* out = (float*)d_out;

    size_t prepBytes = (size_t)(2*EMBD*H1P + RPB*EMBD) * sizeof(float);
    static int configured = -1;
    if (configured < 0) {
        cudaFuncSetAttribute(prep_kernel,
                             cudaFuncAttributeMaxDynamicSharedMemorySize,
                             (int)prepBytes);
        cudaFuncSetAttribute(pair_tc_kernel,
                             cudaFuncAttributeMaxDynamicSharedMemorySize,
                             SMEM_DYN);
        configured = 1;
    }

    prep_kernel<<<PREPBLK, PTHREADS, prepBytes>>>(skills, emb, W1, b1);
    pair_tc_kernel<<<TCGRID, 256, SMEM_DYN>>>(skills, ts, W2, b2, W3, b3);
    final_kernel<<<(ROWS*32 + 255)/256, 256>>>(users, items, langs, skills,
                                               targets, mask, linW, linb, out);
}